// round 6
// baseline (speedup 1.0000x reference)
#include <cuda_runtime.h>
#include <cstdint>

// FRIENDATTN persistent TMA pipeline, 2 rows per iteration.
// Per friend-row n (N=16384): scores = x[n]·self[n/64] (L=50,D=128),
// w = softmax(scores); out[n] = sum_l w[l]*mask[n,l]*x[n,l,:].
//
// Row PAIRS (contiguous 51200B, same user since 64 is even) fetched with one
// cp.async.bulk per stage; 2-stage double buffer; 256 threads; 2 CTAs/SM.
// Softmax for the two rows runs in parallel on warps 0 and 1; barriers are
// amortized 2x vs the 1-row/iter version.

#define D_DIM 128
#define L_DIM 50
#define TPB   256
#define NROWS (256 * 64)
#define NPAIR (NROWS / 2)
#define GRID  304            // 152 SMs * 2 CTAs/SM

#define PAIR_BYTES  (2 * L_DIM * D_DIM * 4)   // 51200
#define SELF_BYTES  (D_DIM * 4)               // 512
#define TX_BYTES    (PAIR_BYTES + SELF_BYTES)

// dynamic SMEM layout (float index):
//  sx     [2][2][6400] @ 0        (stage s at s*12800, row r at +r*6400)
//  sself  [2][128]     @ 25600
//  sscore [2][64]      @ 25856
//  sw     [2][64]      @ 25984
//  mbar   [2] u64      @ 26112
#define OFF_SELF   25600
#define OFF_SCORE  25856
#define OFF_W      25984
#define OFF_MBAR   26112
#define SM_FLOATS  26116

__device__ __forceinline__ unsigned int smem_u32(const void* p)
{
    return (unsigned int)__cvta_generic_to_shared(p);
}
__device__ __forceinline__ void mbar_init(unsigned int mbar, unsigned int count)
{
    asm volatile("mbarrier.init.shared.b64 [%0], %1;" :: "r"(mbar), "r"(count) : "memory");
}
__device__ __forceinline__ void mbar_expect_tx(unsigned int mbar, unsigned int bytes)
{
    asm volatile("mbarrier.arrive.expect_tx.shared.b64 _, [%0], %1;"
                 :: "r"(mbar), "r"(bytes) : "memory");
}
__device__ __forceinline__ void mbar_wait(unsigned int mbar, unsigned int phase)
{
    asm volatile(
        "{\n\t"
        ".reg .pred P;\n\t"
        "W%=:\n\t"
        "mbarrier.try_wait.parity.acquire.cta.shared::cta.b64 P, [%0], %1, 0x989680;\n\t"
        "@!P bra W%=;\n\t"
        "}"
        :: "r"(mbar), "r"(phase) : "memory");
}
__device__ __forceinline__ void bulk_g2s(unsigned int dst, const void* src,
                                         unsigned int bytes, unsigned int mbar)
{
    asm volatile(
        "cp.async.bulk.shared::cta.global.mbarrier::complete_tx::bytes [%0], [%1], %2, [%3];"
        :: "r"(dst), "l"(src), "r"(bytes), "r"(mbar) : "memory");
}

__global__ __launch_bounds__(TPB) void friendattn_kernel(
    const float* __restrict__ x,        // [N, L, D]
    const float* __restrict__ self_x,   // [B, D]
    const void*  __restrict__ mask,     // [N, L]; dtype detected inline
    float* __restrict__ out)            // [N, D]
{
    extern __shared__ float smem[];
    const int tid  = threadIdx.x;
    const int lane = tid & 31;
    const int warp = tid >> 5;

    const unsigned int mbar0 = smem_u32(smem + OFF_MBAR);
    const unsigned int mbar1 = mbar0 + 8;

    // ---- inline mask dtype detection (first 2048 int32 words = 8KB, L2-hot) ----
    int gt1 = 0, odd_nz = 0, even_nz = 0;
    {
        const int* mw = (const int*)mask;
        #pragma unroll
        for (int it = 0; it < 8; ++it) {
            int i = it * TPB + tid;
            unsigned int v = (unsigned int)mw[i];
            if (v > 1u) gt1 = 1;
            if (v != 0u) { if (i & 1) odd_nz = 1; else even_nz = 1; }
        }
    }
    const int any_gt1  = __syncthreads_or(gt1);
    const int any_odd  = __syncthreads_or(odd_nz);
    const int any_even = __syncthreads_or(even_nz);
    const int mode = any_gt1 ? 0 : ((!any_odd && any_even) ? 2 : 1);

    if (tid == 0) {
        mbar_init(mbar0, 1);
        mbar_init(mbar1, 1);
        asm volatile("fence.proxy.async.shared::cta;" ::: "memory");
    }
    __syncthreads();

    // ---- TMA prefetch: one bulk copy for the 2-row tile, one for self ----
    auto prefetch = [&](int pair, int buf) {
        const unsigned int mb = buf ? mbar1 : mbar0;
        mbar_expect_tx(mb, TX_BYTES);
        bulk_g2s(smem_u32(smem + buf * (2 * L_DIM * D_DIM)),
                 x + (size_t)pair * (2 * L_DIM * D_DIM), PAIR_BYTES, mb);
        bulk_g2s(smem_u32(smem + OFF_SELF + buf * D_DIM),
                 self_x + (size_t)(pair >> 5) * D_DIM, SELF_BYTES, mb);
    };

    int pair = blockIdx.x;
    if (tid == 0 && pair < NPAIR) prefetch(pair, 0);

    int buf = 0;
    unsigned int phase[2] = {0u, 0u};

    while (pair < NPAIR) {
        const int nxt = pair + GRID;
        if (tid == 0 && nxt < NPAIR) prefetch(nxt, buf ^ 1);

        // ---- warps 0/1 issue their row's mask loads early (hide under wait) ----
        float fm0 = 0.0f, fm1 = 0.0f;
        if (warp < 2) {
            const long long mbase = (long long)(pair * 2 + warp) * L_DIM;
            if (mode == 0) {
                const unsigned char* m = (const unsigned char*)mask + mbase;
                fm0 = m[lane] ? 1.0f : 0.0f;
                if (lane + 32 < L_DIM) fm1 = m[lane + 32] ? 1.0f : 0.0f;
            } else if (mode == 1) {
                const int* m = (const int*)mask + mbase;
                fm0 = m[lane] ? 1.0f : 0.0f;
                if (lane + 32 < L_DIM) fm1 = m[lane + 32] ? 1.0f : 0.0f;
            } else {
                const int* m = (const int*)mask + 2 * mbase;
                fm0 = m[2 * lane] ? 1.0f : 0.0f;
                if (lane + 32 < L_DIM) fm1 = m[2 * (lane + 32)] ? 1.0f : 0.0f;
            }
        }

        // ---- wait for this stage's TMA ----
        mbar_wait(buf ? mbar1 : mbar0, phase[buf]);
        phase[buf] ^= 1u;

        const float* sself = smem + OFF_SELF + buf * D_DIM;
        float* sscore = smem + OFF_SCORE;
        float* sw     = smem + OFF_W;

        // ---- scores: warp w -> row (w>>2), l = (w&3), step 4 ----
        {
            const int r = warp >> 2;
            const float* sxr = smem + buf * (2 * L_DIM * D_DIM) + r * (L_DIM * D_DIM);
            const float4 s4 = ((const float4*)sself)[lane];
            for (int l = warp & 3; l < L_DIM; l += 4) {
                float4 v = ((const float4*)(sxr + l * D_DIM))[lane];
                float p = v.x * s4.x + v.y * s4.y + v.z * s4.z + v.w * s4.w;
                #pragma unroll
                for (int o = 16; o > 0; o >>= 1) p += __shfl_xor_sync(0xffffffffu, p, o);
                if (lane == 0) sscore[r * 64 + l] = p;
            }
        }
        __syncthreads();

        // ---- softmax: warp 0 -> row 0, warp 1 -> row 1, in parallel ----
        if (warp < 2) {
            const float* sc = sscore + warp * 64;
            float v0 = sc[lane];
            float v1 = (lane + 32 < L_DIM) ? sc[lane + 32] : -3.0e38f;
            float mx = fmaxf(v0, v1);
            #pragma unroll
            for (int o = 16; o > 0; o >>= 1) mx = fmaxf(mx, __shfl_xor_sync(0xffffffffu, mx, o));
            float e0 = __expf(v0 - mx);
            float e1 = (lane + 32 < L_DIM) ? __expf(v1 - mx) : 0.0f;
            float s = e0 + e1;
            #pragma unroll
            for (int o = 16; o > 0; o >>= 1) s += __shfl_xor_sync(0xffffffffu, s, o);
            float inv = 1.0f / s;
            sw[warp * 64 + lane] = e0 * inv * fm0;
            if (lane + 32 < L_DIM) sw[warp * 64 + lane + 32] = e1 * inv * fm1;
        }
        __syncthreads();

        // ---- pooling: thread -> (row r, dim d) ----
        {
            const int r = tid >> 7;
            const int d = tid & 127;
            const float* sxr = smem + buf * (2 * L_DIM * D_DIM) + r * (L_DIM * D_DIM);
            const float* swr = sw + r * 64;
            float acc = 0.0f;
            #pragma unroll
            for (int l = 0; l < L_DIM; ++l)
                acc = fmaf(swr[l], sxr[l * D_DIM + d], acc);
            out[(size_t)(pair * 2 + r) * D_DIM + d] = acc;
        }

        __syncthreads();   // all reads of stage buf done before tid0 refills it
        buf ^= 1;
        pair = nxt;
    }
}

extern "C" void kernel_launch(void* const* d_in, const int* in_sizes, int n_in,
                              void* d_out, int out_size)
{
    const float* x      = (const float*)d_in[0];
    const float* self_x = (const float*)d_in[1];
    const void*  mask   = d_in[n_in - 1];
    float* out = (float*)d_out;

    cudaFuncSetAttribute(friendattn_kernel,
                         cudaFuncAttributeMaxDynamicSharedMemorySize,
                         SM_FLOATS * sizeof(float));

    friendattn_kernel<<<GRID, TPB, SM_FLOATS * sizeof(float)>>>(x, self_x, mask, out);
}